// round 14
// baseline (speedup 1.0000x reference)
#include <cuda_runtime.h>
#include <cuda_fp16.h>
#include <cuda_bf16.h>

#define N_NODES 100000
#define N_EDGES 3200000
#define F_IN 35
#define KPAD 36
#define F_HID 64
#define F_OUT 2
#define FIXP 268435456.0f   // 2^28
#define FIXP_INV (1.0f / 268435456.0f)

// ---- scratch (static; no allocation allowed; zero-initialized at load) ----
__device__ __align__(16) __half g_h1[N_NODES * F_HID];  // dinv * (x@W1), fp16, row-major
__device__ __align__(16) float  g_h2[N_NODES * F_OUT];  // dinv * (layer-2 features)
__device__ unsigned long long g_acc[N_NODES];  // hi24: count, lo40: sum(ew)*2^28 (self-cleaned)
__device__ float g_dinv[N_NODES];
__device__ __align__(8) int2 g_seg[N_NODES];   // (beg, end) of node's CSR segment
__device__ int   g_cursor;                     // CSR cursor (self-cleaned by k_gemm_fill)
__device__ __align__(16) int g_rank[N_EDGES];  // per-edge slot within its dst segment
__device__ __align__(8) int2 g_csr[N_EDGES];   // (src byte-offset = src<<7, ew bits)

// ---------------- edge scatter (4 edges/thread): counts + weighted degree + rank ----
__global__ void __launch_bounds__(256) k_scatter(const int* __restrict__ ei,
                                                 const float* __restrict__ ew, int ne) {
    int e0 = (blockIdx.x * 256 + threadIdx.x) * 4;
    if (e0 + 3 < ne) {
        float4 w4 = *reinterpret_cast<const float4*>(ew + e0);  // e0 % 4 == 0
        int d0 = ei[ne + e0], d1 = ei[ne + e0 + 1];
        int d2 = ei[ne + e0 + 2], d3 = ei[ne + e0 + 3];
        unsigned long long o0 = atomicAdd(&g_acc[d0], (1ULL << 40) | (unsigned long long)(w4.x * FIXP));
        unsigned long long o1 = atomicAdd(&g_acc[d1], (1ULL << 40) | (unsigned long long)(w4.y * FIXP));
        unsigned long long o2 = atomicAdd(&g_acc[d2], (1ULL << 40) | (unsigned long long)(w4.z * FIXP));
        unsigned long long o3 = atomicAdd(&g_acc[d3], (1ULL << 40) | (unsigned long long)(w4.w * FIXP));
        *reinterpret_cast<int4*>(g_rank + e0) =
            make_int4((int)(o0 >> 40), (int)(o1 >> 40), (int)(o2 >> 40), (int)(o3 >> 40));
    } else {
        for (int e = e0; e < ne; e++) {
            int dst = ei[ne + e];
            unsigned long long old = atomicAdd(&g_acc[dst],
                (1ULL << 40) | (unsigned long long)(ew[e] * FIXP));
            g_rank[e] = (int)(old >> 40);
        }
    }
}

// ---- base: dinv + seg alloc (block scan + cursor atomic) + acc self-clean ----
__global__ void __launch_bounds__(256) k_base(int n) {
    __shared__ int swarp[8];
    __shared__ int sbase;
    int t = threadIdx.x, lane = t & 31, wid = t >> 5;
    int i = blockIdx.x * 256 + t;
    int c = 0;
    if (i < n) {
        unsigned long long a = g_acc[i];
        g_acc[i] = 0ULL;                    // self-clean for next replay
        c = (int)(a >> 40);
        float deg = 1.0f + (float)(a & ((1ULL << 40) - 1)) * FIXP_INV;
        g_dinv[i] = rsqrtf(deg);
    }
    int v = c;
#pragma unroll
    for (int o = 1; o < 32; o <<= 1) {
        int u = __shfl_up_sync(0xFFFFFFFFu, v, o);
        if (lane >= o) v += u;
    }
    if (lane == 31) swarp[wid] = v;
    __syncthreads();
    if (wid == 0) {
        int s = (lane < 8) ? swarp[lane] : 0;
#pragma unroll
        for (int o = 1; o < 8; o <<= 1) {
            int u = __shfl_up_sync(0xFFFFFFFFu, s, o);
            if (lane >= o) s += u;
        }
        if (lane < 8) swarp[lane] = s;
        if (lane == 7) sbase = atomicAdd(&g_cursor, s);
    }
    __syncthreads();
    int excl = v - c + (wid > 0 ? swarp[wid - 1] : 0);
    if (i < n) {
        int beg = sbase + excl;
        g_seg[i] = make_int2(beg, beg + c);
    }
}

// ---------------- fused: layer-1 GEMM (h1' = dinv*x@W1, 2 cols/lane) || CSR fill ----
__global__ void __launch_bounds__(256) k_gemm_fill(
        const int* __restrict__ ei, const float* __restrict__ ew,
        const float* __restrict__ x, const float* __restrict__ W1,
        int n, int ne, int nblk_gm) {
    __shared__ float2 sW2[KPAD][32];      // [k][lane] -> cols (2l, 2l+1)
    __shared__ float  sx[8][2][KPAD];

    if (blockIdx.x >= (unsigned)nblk_gm) {
        // ---- CSR fill part (4 edges/thread): (src<<7, ew) ----
        if (blockIdx.x == (unsigned)nblk_gm && threadIdx.x == 0)
            g_cursor = 0;   // self-clean for next replay
        int e0 = ((blockIdx.x - nblk_gm) * 256 + threadIdx.x) * 4;
        if (e0 + 3 < ne) {
            int4   s4 = *reinterpret_cast<const int4*>(ei + e0);       // e0 % 4 == 0
            float4 w4 = *reinterpret_cast<const float4*>(ew + e0);
            int4   r4 = *reinterpret_cast<const int4*>(g_rank + e0);
            int d0 = ei[ne + e0], d1 = ei[ne + e0 + 1];
            int d2 = ei[ne + e0 + 2], d3 = ei[ne + e0 + 3];
            g_csr[g_seg[d0].x + r4.x] = make_int2(s4.x << 7, __float_as_int(w4.x));
            g_csr[g_seg[d1].x + r4.y] = make_int2(s4.y << 7, __float_as_int(w4.y));
            g_csr[g_seg[d2].x + r4.z] = make_int2(s4.z << 7, __float_as_int(w4.z));
            g_csr[g_seg[d3].x + r4.w] = make_int2(s4.w << 7, __float_as_int(w4.w));
        } else {
            for (int e = e0; e < ne; e++) {
                int src = ei[e];
                int dst = ei[ne + e];
                g_csr[g_seg[dst].x + g_rank[e]] = make_int2(src << 7, __float_as_int(ew[e]));
            }
        }
        return;
    }

    // ---- gemm1 part: h1' = dinv[row] * (x[row] @ W1), 2 rows/warp, 2 cols/lane ----
    int t = threadIdx.x, w = t >> 5, lane = t & 31;
    for (int i = t; i < KPAD * 32; i += 256) {
        int k = i >> 5, l = i & 31;
        float2 v = make_float2(0.f, 0.f);
        if (k < F_IN) { v.x = W1[k * F_HID + 2 * l]; v.y = W1[k * F_HID + 2 * l + 1]; }
        sW2[k][l] = v;
    }
    int row0 = blockIdx.x * 16 + w * 2;
#pragma unroll
    for (int r = 0; r < 2; r++) {
        int row = row0 + r;
        if (row < n) {
            sx[w][r][lane] = x[(size_t)row * F_IN + lane];
            if (lane < 4) sx[w][r][32 + lane] =
                (lane < F_IN - 32) ? x[(size_t)row * F_IN + 32 + lane] : 0.f;
        }
    }
    __syncthreads();
    if (row0 >= n) return;

    float acc00 = 0.f, acc01 = 0.f, acc10 = 0.f, acc11 = 0.f;
    const float4* sx40 = reinterpret_cast<const float4*>(sx[w][0]);
    const float4* sx41 = reinterpret_cast<const float4*>(sx[w][1]);
#pragma unroll
    for (int k4 = 0; k4 < KPAD / 4; k4++) {
        float4 x0 = sx40[k4], x1 = sx41[k4];
#pragma unroll
        for (int i = 0; i < 4; i++) {
            float2 wv = sW2[k4 * 4 + i][lane];
            float xv0 = (&x0.x)[i], xv1 = (&x1.x)[i];
            acc00 += xv0 * wv.x; acc01 += xv0 * wv.y;
            acc10 += xv1 * wv.x; acc11 += xv1 * wv.y;
        }
    }
    float dv0 = g_dinv[row0];
    reinterpret_cast<__half2*>(g_h1 + (size_t)row0 * F_HID)[lane] =
        __floats2half2_rn(dv0 * acc00, dv0 * acc01);
    if (row0 + 1 < n) {
        float dv1 = g_dinv[row0 + 1];
        reinterpret_cast<__half2*>(g_h1 + (size_t)(row0 + 1) * F_HID)[lane] =
            __floats2half2_rn(dv1 * acc10, dv1 * acc11);
    }
}

// ---- agg1: half-warp edge parallelism (2 edges/iter, 8B/lane) + relu + b1 + W2 GEMV ----
__global__ void __launch_bounds__(256) k_agg1(const float* __restrict__ W2,
                                              const float* __restrict__ b1, int n) {
    __shared__ int2 stage[8][32];
    int wi = threadIdx.x >> 5;
    int lane = threadIdx.x & 31;
    int h = lane >> 4;        // half-warp id: processes edges i+h
    int c = lane & 15;        // chunk id: owns cols 4c..4c+3 (8 bytes)
    int w = blockIdx.x * 8 + wi;
    if (w >= n) return;
    int2 seg = g_seg[w];
    int beg = seg.x, end = seg.y;
    float dv = g_dinv[w];
    const char* h1b = reinterpret_cast<const char*>(g_h1);
    int coff = c << 3;

    // self term only in half 0 (halves are summed at the end)
    float a0 = 0.f, a1 = 0.f, a2 = 0.f, a3 = 0.f;
    if (h == 0) {
        uint2 sr = *reinterpret_cast<const uint2*>(h1b + ((size_t)w << 7) + coff);
        float2 s0 = __half22float2(*reinterpret_cast<const __half2*>(&sr.x));
        float2 s1 = __half22float2(*reinterpret_cast<const __half2*>(&sr.y));
        a0 = s0.x; a1 = s0.y; a2 = s1.x; a3 = s1.y;
    }

    for (int j0 = beg; j0 < end; j0 += 32) {
        int j = j0 + lane;
        if (j < end) stage[wi][lane] = g_csr[j];
        __syncwarp();
        int cnt = end - j0; if (cnt > 32) cnt = 32;
        int i = 0;
        for (; i + 8 <= cnt; i += 8) {   // 4 iterations x 2 edges
            int2 e0 = stage[wi][i + h];
            int2 e1 = stage[wi][i + 2 + h];
            int2 e2 = stage[wi][i + 4 + h];
            int2 e3 = stage[wi][i + 6 + h];
            uint2 r0 = *reinterpret_cast<const uint2*>(h1b + e0.x + coff);
            uint2 r1 = *reinterpret_cast<const uint2*>(h1b + e1.x + coff);
            uint2 r2 = *reinterpret_cast<const uint2*>(h1b + e2.x + coff);
            uint2 r3 = *reinterpret_cast<const uint2*>(h1b + e3.x + coff);
            float n0 = __int_as_float(e0.y), n1 = __int_as_float(e1.y);
            float n2 = __int_as_float(e2.y), n3 = __int_as_float(e3.y);
            float2 f;
            f = __half22float2(*reinterpret_cast<const __half2*>(&r0.x)); a0 += n0 * f.x; a1 += n0 * f.y;
            f = __half22float2(*reinterpret_cast<const __half2*>(&r0.y)); a2 += n0 * f.x; a3 += n0 * f.y;
            f = __half22float2(*reinterpret_cast<const __half2*>(&r1.x)); a0 += n1 * f.x; a1 += n1 * f.y;
            f = __half22float2(*reinterpret_cast<const __half2*>(&r1.y)); a2 += n1 * f.x; a3 += n1 * f.y;
            f = __half22float2(*reinterpret_cast<const __half2*>(&r2.x)); a0 += n2 * f.x; a1 += n2 * f.y;
            f = __half22float2(*reinterpret_cast<const __half2*>(&r2.y)); a2 += n2 * f.x; a3 += n2 * f.y;
            f = __half22float2(*reinterpret_cast<const __half2*>(&r3.x)); a0 += n3 * f.x; a1 += n3 * f.y;
            f = __half22float2(*reinterpret_cast<const __half2*>(&r3.y)); a2 += n3 * f.x; a3 += n3 * f.y;
        }
        for (; i + 2 <= cnt; i += 2) {
            int2 e0 = stage[wi][i + h];
            uint2 r0 = *reinterpret_cast<const uint2*>(h1b + e0.x + coff);
            float n0 = __int_as_float(e0.y);
            float2 f;
            f = __half22float2(*reinterpret_cast<const __half2*>(&r0.x)); a0 += n0 * f.x; a1 += n0 * f.y;
            f = __half22float2(*reinterpret_cast<const __half2*>(&r0.y)); a2 += n0 * f.x; a3 += n0 * f.y;
        }
        if (i < cnt) {   // odd leftover: both halves load it, half 1 contributes 0
            int2 e0 = stage[wi][i];
            uint2 r0 = *reinterpret_cast<const uint2*>(h1b + e0.x + coff);
            float n0 = (h == 0) ? __int_as_float(e0.y) : 0.f;
            float2 f;
            f = __half22float2(*reinterpret_cast<const __half2*>(&r0.x)); a0 += n0 * f.x; a1 += n0 * f.y;
            f = __half22float2(*reinterpret_cast<const __half2*>(&r0.y)); a2 += n0 * f.x; a3 += n0 * f.y;
        }
        __syncwarp();
    }

    // combine the two half-warps
    a0 += __shfl_xor_sync(0xFFFFFFFFu, a0, 16);
    a1 += __shfl_xor_sync(0xFFFFFFFFu, a1, 16);
    a2 += __shfl_xor_sync(0xFFFFFFFFu, a2, 16);
    a3 += __shfl_xor_sync(0xFFFFFFFFu, a3, 16);

    a0 *= dv; a1 *= dv; a2 *= dv; a3 *= dv;

    float h0 = fmaxf(a0 + b1[4 * c + 0], 0.f);
    float h1v = fmaxf(a1 + b1[4 * c + 1], 0.f);
    float h2v = fmaxf(a2 + b1[4 * c + 2], 0.f);
    float h3v = fmaxf(a3 + b1[4 * c + 3], 0.f);
    float p0 = h0 * W2[(4 * c + 0) * 2 + 0] + h1v * W2[(4 * c + 1) * 2 + 0]
             + h2v * W2[(4 * c + 2) * 2 + 0] + h3v * W2[(4 * c + 3) * 2 + 0];
    float p1 = h0 * W2[(4 * c + 0) * 2 + 1] + h1v * W2[(4 * c + 1) * 2 + 1]
             + h2v * W2[(4 * c + 2) * 2 + 1] + h3v * W2[(4 * c + 3) * 2 + 1];
#pragma unroll
    for (int o = 8; o > 0; o >>= 1) {
        p0 += __shfl_xor_sync(0xFFFFFFFFu, p0, o);
        p1 += __shfl_xor_sync(0xFFFFFFFFu, p1, o);
    }
    if (lane == 0) {
        g_h2[w * 2 + 0] = dv * p0;   // h2' = dinv * h2
        g_h2[w * 2 + 1] = dv * p1;
    }
}

// ---------------- agg2: A = dv*(Σ ew*h2'[src] + h2'[w]) + b2; log_softmax ----------------
__global__ void __launch_bounds__(256) k_agg2(const float* __restrict__ b2,
                                              float* __restrict__ out, int n) {
    int w = (blockIdx.x * blockDim.x + threadIdx.x) >> 5;
    int lane = threadIdx.x & 31;
    if (w >= n) return;
    int2 seg = g_seg[w];
    const char* h2b = reinterpret_cast<const char*>(g_h2);
    float a0 = 0.f, a1 = 0.f;
    for (int j = seg.x + lane; j < seg.y; j += 32) {
        int2 e = g_csr[j];
        float nm = __int_as_float(e.y);
        // e.x = src<<7; h2 byte offset = src*8 = e.x>>4
        float2 v = *reinterpret_cast<const float2*>(h2b + (e.x >> 4));
        a0 += nm * v.x;
        a1 += nm * v.y;
    }
#pragma unroll
    for (int o = 16; o > 0; o >>= 1) {
        a0 += __shfl_xor_sync(0xFFFFFFFFu, a0, o);
        a1 += __shfl_xor_sync(0xFFFFFFFFu, a1, o);
    }
    if (lane == 0) {
        float dv = g_dinv[w];
        float2 hv = *reinterpret_cast<const float2*>(g_h2 + (size_t)w * 2);
        float A = dv * (a0 + hv.x) + b2[0];
        float B = dv * (a1 + hv.y) + b2[1];
        float m = fmaxf(A, B);
        float lse = m + logf(expf(A - m) + expf(B - m));
        out[w * 2 + 0] = A - lse;
        out[w * 2 + 1] = B - lse;
    }
}

extern "C" void kernel_launch(void* const* d_in, const int* in_sizes, int n_in,
                              void* d_out, int out_size) {
    const float* x  = (const float*)d_in[0];
    const int*   ei = (const int*)d_in[1];   // int32 (JAX x64 disabled)
    const float* ew = (const float*)d_in[2];
    const float* W1 = (const float*)d_in[3];
    const float* b1 = (const float*)d_in[4];
    const float* W2 = (const float*)d_in[5];
    const float* b2 = (const float*)d_in[6];
    float* out = (float*)d_out;

    const int n  = in_sizes[0] / F_IN;   // 100000
    const int ne = in_sizes[2];          // 3200000

    const int nq = (ne + 3) / 4;                   // 4 edges per edge-stream thread
    const int nblk_ed = (nq + 255) / 256;
    const int nblk_gm = (n + 15) / 16;
    k_scatter<<<nblk_ed, 256>>>(ei, ew, ne);
    k_base<<<(n + 255) / 256, 256>>>(n);
    k_gemm_fill<<<nblk_gm + nblk_ed, 256>>>(ei, ew, x, W1, n, ne, nblk_gm);
    k_agg1<<<(n + 7) / 8, 256>>>(W2, b1, n);
    k_agg2<<<(n * 32 + 255) / 256, 256>>>(b2, out, n);
}